// round 7
// baseline (speedup 1.0000x reference)
#include <cuda_runtime.h>
#include <cuda_bf16.h>
#include <math_constants.h>

// Problem constants (fixed by the benchmark)
#define BB 2
#define LL 2048
#define HH 8
#define DD 64
#define UU 80
#define SS 80
#define BHN (BB*HH)
#define SPLIT 16
#define CHUNK (LL/SPLIT)      // 128 keys per split block
#define UST 8                 // u-stride for winner loop

// Sample kernel tiling
#define LT 128                // l rows per block
#define NKT 8                 // 8 key tiles of 256 keys
#define KT 256
#define BLKS_PER_BH (LL/LT)   // 16 sample blocks per (b,h)

// Scratch (device globals; zero-initialized at module load)
__device__ float g_M[BB*HH*LL];           // sparsity measure M[b,h,l]
__device__ float g_vmean[BHN*DD];         // V column sums (atomic), re-zeroed after use
__device__ int   g_cb[BHN];               // per-bh completion counter (self-reset)
__device__ int   g_cu[BHN*UU];            // per-(bh,u) split counter (self-reset)
__device__ int   g_nw[BHN];               // winners per (b,h)
__device__ int   g_wl[BHN*UU];            // winner: source token l
__device__ int   g_wj[BHN*UU];            // winner: output slot j
__device__ float g_pmax[BHN*UU*SPLIT];    // split-softmax partial max
__device__ float g_psum[BHN*UU*SPLIT];    // split-softmax partial sum(exp)
__device__ float g_pv  [BHN*UU*SPLIT*DD]; // split partial (unnormalized) PV

// ---------------------------------------------------------------------------
// Kernel 1: tile-phased sampled scores (L1-resident K tiles) + V sums +
// (last block per bh) top-80.
// Block = 1024 threads, 128 l-rows. Build per-l tile-bucketed sample lists in
// smem, then loop the 8 key tiles with ALL warps on the same tile (barrier per
// tile) so each 64KB K tile is pulled from L2 once and gathers hit L1.
// Gather math identical to the validated R5 kernel: 8-lane groups, 4
// predicated sampled dots per warp-iteration via LDG.128 + 3 shfl.
// ---------------------------------------------------------------------------
__global__ void __launch_bounds__(1024, 1)
k_sample_topk(const float* __restrict__ Q, const float* __restrict__ K,
              const float* __restrict__ V, const int* __restrict__ idx,
              float* __restrict__ out) {
    __shared__ unsigned short sj[LT*SS];       // per-l tile-sorted sample indices
    __shared__ unsigned char  soff[LT][NKT+1]; // per-l bucket offsets (<=80)
    __shared__ float smax[LT];
    __shared__ float ssum[LT];
    __shared__ float vtmp[16][DD];
    __shared__ int   isLast;
    // top-k state (last block per bh only)
    __shared__ unsigned su[LL];
    __shared__ int hist[256];
    __shared__ int scnt2[2];
    __shared__ unsigned long long keys[128];
    __shared__ int eqbuf[256];
    __shared__ int cgt, ceq;
    __shared__ int stopA[UU];
    __shared__ int win[UU];
    __shared__ float meanS[DD];

    int t = threadIdx.x, lane = t & 31, warp = t >> 5;
    int bh = blockIdx.y;
    int b = bh >> 3, h = bh & 7;
    int l0 = blockIdx.x * LT;

    // ---- V partial column sums for this l-tile (coalesced) ----
    {
        int rg = t >> 6, d = t & 63;
        float s = 0.f;
        #pragma unroll 8
        for (int l = rg; l < LT; l += 16)
            s += V[(((size_t)b*LL + l0 + l)*HH + h)*DD + d];
        vtmp[rg][d] = s;
    }

    // ---- bucket build: owner thread per l sorts its 80 samples by key tile ----
    if (t < LT) {
        const int4* ir = (const int4*)(idx + (size_t)(l0 + t)*SS);
        int c[NKT];
        #pragma unroll
        for (int i = 0; i < NKT; ++i) c[i] = 0;
        #pragma unroll 5
        for (int q4 = 0; q4 < SS/4; ++q4) {
            int4 v = ir[q4];
            c[v.x >> 8]++; c[v.y >> 8]++; c[v.z >> 8]++; c[v.w >> 8]++;
        }
        int off[NKT+1]; off[0] = 0;
        #pragma unroll
        for (int i = 0; i < NKT; ++i) off[i+1] = off[i] + c[i];
        #pragma unroll
        for (int i = 0; i <= NKT; ++i) soff[t][i] = (unsigned char)off[i];
        int cur[NKT];
        #pragma unroll
        for (int i = 0; i < NKT; ++i) cur[i] = off[i];
        #pragma unroll 5
        for (int q4 = 0; q4 < SS/4; ++q4) {
            int4 v = ir[q4];
            sj[t*SS + cur[v.x >> 8]++] = (unsigned short)v.x;
            sj[t*SS + cur[v.y >> 8]++] = (unsigned short)v.y;
            sj[t*SS + cur[v.z >> 8]++] = (unsigned short)v.z;
            sj[t*SS + cur[v.w >> 8]++] = (unsigned short)v.w;
        }
        smax[t] = -CUDART_INF_F;
        ssum[t] = 0.f;
    }
    __syncthreads();

    // finish V sums (one atomic per d)
    if (t < DD) {
        float s = 0.f;
        #pragma unroll
        for (int i = 0; i < 16; ++i) s += vtmp[i][t];
        atomicAdd(&g_vmean[bh*DD + t], s);
    }

    // ---- main loop: all warps on the same K tile (L1-resident) ----
    int grp = lane >> 3, lg = lane & 7;
    for (int kt = 0; kt < NKT; ++kt) {
        #pragma unroll
        for (int li = 0; li < 4; ++li) {
            int lloc = warp*4 + li;
            int s0 = soff[lloc][kt], s1 = soff[lloc][kt+1];
            if (s1 > s0) {
                const float* qrow = Q + (((size_t)b*LL + l0 + lloc)*HH + h)*DD + lg*8;
                float4 q0 = *(const float4*)(qrow);
                float4 q1 = *(const float4*)(qrow + 4);
                float vmax = -CUDART_INF_F, vsum = 0.f;
                int nit = (s1 - s0 + 3) >> 2;
                for (int it = 0; it < nit; ++it) {
                    int s = s0 + it*4 + grp;
                    bool ok = s < s1;
                    int sc = ok ? s : (s1 - 1);          // clamp: stay in hot tile
                    int j = sj[lloc*SS + sc];
                    const float* kr = K + (((size_t)b*LL + j)*HH + h)*DD + lg*8;
                    float4 k0 = *(const float4*)(kr);
                    float4 k1 = *(const float4*)(kr + 4);
                    float p = q0.x*k0.x + q0.y*k0.y + q0.z*k0.z + q0.w*k0.w
                            + q1.x*k1.x + q1.y*k1.y + q1.z*k1.z + q1.w*k1.w;
                    p += __shfl_xor_sync(0xffffffffu, p, 4);
                    p += __shfl_xor_sync(0xffffffffu, p, 2);
                    p += __shfl_xor_sync(0xffffffffu, p, 1);
                    if (ok) { vmax = fmaxf(vmax, p); vsum += p; }
                }
                vmax = fmaxf(vmax, __shfl_xor_sync(0xffffffffu, vmax, 8));
                vmax = fmaxf(vmax, __shfl_xor_sync(0xffffffffu, vmax, 16));
                vsum += __shfl_xor_sync(0xffffffffu, vsum, 8);
                vsum += __shfl_xor_sync(0xffffffffu, vsum, 16);
                if (lane == 0) {
                    smax[lloc] = fmaxf(smax[lloc], vmax);   // single-owner, no atomics
                    ssum[lloc] += vsum;
                }
            }
        }
        __syncthreads();    // keep all warps phase-locked on one tile (L1)
    }

    // ---- finalize M for this l-tile ----
    if (t < LT)
        g_M[bh*LL + l0 + t] = smax[t] - ssum[t] * (1.0f/(float)LL);

    // ---- completion protocol: last block of this bh runs top-k inline ----
    __threadfence();
    __syncthreads();
    if (t == 0) {
        int old = atomicAdd(&g_cb[bh], 1);
        isLast = (old == BLKS_PER_BH - 1);
    }
    __syncthreads();
    if (!isLast) return;
    if (t == 0) g_cb[bh] = 0;                  // self-reset for next replay

    // ======================= top-k body (last block) =======================
    if (t < DD) {
        meanS[t] = g_vmean[bh*DD + t] * (1.0f/(float)LL);
        g_vmean[bh*DD + t] = 0.f;
    }
    for (int i = t; i < LL; i += 1024) {
        unsigned bb = __float_as_uint(g_M[bh*LL + i]);
        su[i] = (bb & 0x80000000u) ? ~bb : (bb | 0x80000000u);
    }
    __syncthreads();

    // broadcast-fill all 80 output rows with V_mean (winners overwritten later)
    for (int e = t; e < UU*DD; e += 1024) {
        int j = e >> 6, d = e & 63;
        out[(((size_t)b*UU + j)*HH + h)*DD + d] = meanS[d];
    }

    // 4-pass byte radix: T = 80th-largest transformed value
    unsigned prefix = 0, prefmask = 0;
    int need = UU;
    for (int pass = 0; pass < 4; ++pass) {
        int shift = 24 - pass*8;
        if (t < 256) hist[t] = 0;
        __syncthreads();
        for (int i = t; i < LL; i += 1024) {
            unsigned u = su[i];
            if ((u & prefmask) == prefix) atomicAdd(&hist[(u >> shift) & 0xFF], 1);
        }
        __syncthreads();
        if (t < 32) {
            int base = 255 - t*8;
            int s = 0;
            #pragma unroll
            for (int e = 0; e < 8; ++e) s += hist[base - e];
            int pre = s;
            #pragma unroll
            for (int o = 1; o < 32; o <<= 1) {
                int v = __shfl_up_sync(0xffffffffu, pre, o);
                if (lane >= o) pre += v;
            }
            int excl = pre - s;
            if (excl < need && need <= pre) {
                int acc = excl;
                #pragma unroll
                for (int e = 0; e < 8; ++e) {
                    int hb = hist[base - e];
                    if (acc + hb >= need) { scnt2[0] = base - e; scnt2[1] = acc; break; }
                    acc += hb;
                }
            }
        }
        __syncthreads();
        prefix |= ((unsigned)scnt2[0]) << shift;
        prefmask |= 0xFFu << shift;
        need -= scnt2[1];
        __syncthreads();
    }
    unsigned T = prefix;

    if (t == 0) { cgt = 0; ceq = 0; }
    __syncthreads();
    for (int i = t; i < LL; i += 1024) {
        unsigned u = su[i];
        if (u > T) {
            int p = atomicAdd(&cgt, 1);
            keys[p] = ((unsigned long long)u << 32) | (unsigned)(~i);
        } else if (u == T) {
            int p = atomicAdd(&ceq, 1);
            if (p < 256) eqbuf[p] = i;
        }
    }
    __syncthreads();
    if (t == 0) {
        int base = cgt;
        int ce = min(ceq, 256);
        for (int k = 0; k < need; ++k) {
            int mi = 0x7fffffff, mp = -1;
            for (int e = 0; e < ce; ++e)
                if (eqbuf[e] < mi) { mi = eqbuf[e]; mp = e; }
            keys[base + k] = ((unsigned long long)T << 32) | (unsigned)(~mi);
            eqbuf[mp] = 0x7fffffff;
        }
    }
    if (t < 128 && t >= UU) keys[t] = 0ULL;
    __syncthreads();

    // bitonic sort, 128 elements, descending (=> value desc, index asc)
    for (int ksz = 2; ksz <= 128; ksz <<= 1) {
        for (int jst = ksz >> 1; jst > 0; jst >>= 1) {
            __syncthreads();
            if (t < 128) {
                int ixj = t ^ jst;
                if (ixj > t) {
                    unsigned long long a = keys[t], cc = keys[ixj];
                    bool up = (t & ksz) == 0;
                    if (up ? (a < cc) : (a > cc)) { keys[t] = cc; keys[ixj] = a; }
                }
            }
        }
    }
    __syncthreads();

    if (t < UU) {
        stopA[t] = (int)(~(unsigned)(keys[t] & 0xffffffffu));
        win[t] = -1;
    }
    __syncthreads();
    if (t == 0) {
        for (int u = 0; u < UU; ++u) { int jj = min(stopA[u], UU-1); win[jj] = u; }
        int n2 = 0;
        for (int jj = 0; jj < UU; ++jj) {
            if (win[jj] >= 0) {
                g_wl[bh*UU + n2] = stopA[win[jj]];
                g_wj[bh*UU + n2] = jj;
                n2++;
            }
        }
        g_nw[bh] = n2;
    }
}

// ---------------------------------------------------------------------------
// Kernel 2: split-K attention partials for winner rows with last-split-block
// combine. SPLIT=16, CHUNK=128, 256 threads, grid (bh, UST, SPLIT).
// ---------------------------------------------------------------------------
__global__ void k_attn(const float* __restrict__ Q, const float* __restrict__ K,
                       const float* __restrict__ V, float* __restrict__ out) {
    int bh = blockIdx.x;
    int n = g_nw[bh];
    int b = bh >> 3, h = bh & 7;
    int sp = blockIdx.z, k0 = sp * CHUNK;

    __shared__ float q[DD];
    __shared__ float p[CHUNK];
    __shared__ float red[8];
    __shared__ float ac[4][64];
    __shared__ int lastf;
    int t = threadIdx.x, lane = t & 31, warp = t >> 5;
    int grp = lane >> 3, lg = lane & 7;

    for (int u = blockIdx.y; u < n; u += UST) {
        int l = g_wl[bh*UU + u];
        if (t < DD) q[t] = Q[(((size_t)b*LL + l)*HH + h)*DD + t];
        __syncthreads();
        float4 q0 = ((float4*)q)[lg*2];
        float4 q1 = ((float4*)q)[lg*2 + 1];

        // scores: each warp owns 16 keys, 4 per iteration (one per 8-lane group)
        float lmax = -CUDART_INF_F;
        #pragma unroll
        for (int it = 0; it < 4; ++it) {
            int kk = warp*16 + it*4 + grp;
            const float* kr = K + (((size_t)b*LL + k0 + kk)*HH + h)*DD + lg*8;
            float4 k0v = *(const float4*)kr;
            float4 k1v = *(const float4*)(kr + 4);
            float s = q0.x*k0v.x + q0.y*k0v.y + q0.z*k0v.z + q0.w*k0v.w
                    + q1.x*k1v.x + q1.y*k1v.y + q1.z*k1v.z + q1.w*k1v.w;
            s += __shfl_xor_sync(0xffffffffu, s, 4);
            s += __shfl_xor_sync(0xffffffffu, s, 2);
            s += __shfl_xor_sync(0xffffffffu, s, 1);
            s *= 0.125f;                 // 1/sqrt(64)
            if (lg == 0) p[kk] = s;
            lmax = fmaxf(lmax, s);
        }
        lmax = fmaxf(lmax, __shfl_xor_sync(0xffffffffu, lmax, 8));
        lmax = fmaxf(lmax, __shfl_xor_sync(0xffffffffu, lmax, 16));
        if (lane == 0) red[warp] = lmax;
        __syncthreads();
        if (t == 0) { float m = red[0]; for (int w = 1; w < 8; ++w) m = fmaxf(m, red[w]); red[0] = m; }
        __syncthreads();
        float m = red[0];
        __syncthreads();

        float e = 0.f;
        if (t < CHUNK) { e = __expf(p[t] - m); p[t] = e; }
        float ls = e;
        #pragma unroll
        for (int o = 16; o; o >>= 1) ls += __shfl_xor_sync(0xffffffffu, ls, o);
        if (lane == 0) red[warp] = ls;
        __syncthreads();
        float ssumv = red[0]+red[1]+red[2]+red[3]+red[4]+red[5]+red[6]+red[7];

        // partial PV: 4 key-groups x 64 d-threads, coalesced V reads
        int g4 = t >> 6, d = t & 63;
        float acc = 0.f;
        #pragma unroll 8
        for (int kk = g4; kk < CHUNK; kk += 4)
            acc += p[kk] * V[(((size_t)b*LL + k0 + kk)*HH + h)*DD + d];
        ac[g4][d] = acc;
        __syncthreads();
        int base = (bh*UU + u)*SPLIT + sp;
        if (t < 64)
            g_pv[(size_t)base*DD + t] = ac[0][t] + ac[1][t] + ac[2][t] + ac[3][t];
        if (t == 0) { g_pmax[base] = m; g_psum[base] = ssumv; }

        // ---- last split block for this (bh,u) combines and writes out ----
        __threadfence();
        __syncthreads();
        if (t == 0) {
            int old = atomicAdd(&g_cu[bh*UU + u], 1);
            lastf = (old == SPLIT - 1);
        }
        __syncthreads();
        if (lastf) {
            if (t == 0) g_cu[bh*UU + u] = 0;   // self-reset for replay
            if (t < 64) {
                int cb = (bh*UU + u)*SPLIT;
                float mm = -CUDART_INF_F;
                #pragma unroll
                for (int i = 0; i < SPLIT; ++i) mm = fmaxf(mm, g_pmax[cb + i]);
                float s = 0.f, pv = 0.f;
                #pragma unroll
                for (int i = 0; i < SPLIT; ++i) {
                    float w = __expf(g_pmax[cb + i] - mm);
                    s  += g_psum[cb + i] * w;
                    pv += g_pv[(size_t)(cb + i)*DD + t] * w;
                }
                int j = g_wj[bh*UU + u];
                out[(((size_t)b*UU + j)*HH + h)*DD + t] = pv / s;
            }
        }
        __syncthreads();                 // smem reuse across u iterations
    }
}

// ---------------------------------------------------------------------------
extern "C" void kernel_launch(void* const* d_in, const int* in_sizes, int n_in,
                              void* d_out, int out_size) {
    const float* Q   = (const float*)d_in[0];
    const float* K   = (const float*)d_in[1];
    const float* V   = (const float*)d_in[2];
    const int*   idx = (const int*)d_in[3];
    float* out = (float*)d_out;

    dim3 gs(BLKS_PER_BH, BHN);
    k_sample_topk<<<gs, 1024>>>(Q, K, V, idx, out);
    dim3 ga(BHN, UST, SPLIT);
    k_attn<<<ga, 256>>>(Q, K, V, out);
}

// round 8
// speedup vs baseline: 1.0357x; 1.0357x over previous
#include <cuda_runtime.h>
#include <cuda_bf16.h>
#include <math_constants.h>

// Problem constants (fixed by the benchmark)
#define BB 2
#define LL 2048
#define HH 8
#define DD 64
#define UU 80
#define SS 80
#define BHN (BB*HH)
#define SPLIT 16
#define CHUNK (LL/SPLIT)      // 128 keys per split block
#define UST 8                 // u-stride for winner loop
#define BLKS_PER_BH 256       // k_sample blocks per (b,h)

// Scratch (device globals; zero-initialized at module load)
__device__ float g_M[BB*HH*LL];           // sparsity measure M[b,h,l]
__device__ float g_vmean[BHN*DD];         // V column sums (atomic), re-zeroed after use
__device__ int   g_cb[BHN];               // per-bh completion counter (self-reset)
__device__ int   g_cu[BHN*UU];            // per-(bh,u) split counter (self-reset)
__device__ int   g_nw[BHN];               // winners per (b,h)
__device__ int   g_wl[BHN*UU];            // winner: source token l
__device__ int   g_wj[BHN*UU];            // winner: output slot j
__device__ float g_pmax[BHN*UU*SPLIT];    // split-softmax partial max
__device__ float g_psum[BHN*UU*SPLIT];    // split-softmax partial sum(exp)
__device__ float g_pv  [BHN*UU*SPLIT*DD]; // split partial (unnormalized) PV

// ---------------------------------------------------------------------------
// Kernel 1: sampled scores -> M[b,h,l] fused with V column sums; last block
// per (b,h) runs top-80 (radix select + bitonic, exact jax.lax.top_k
// semantics), winner replay, V_mean fill.
//
// R8 change vs the validated R5 version: each warp first counting-sorts its
// 80 sample indices by key tile (j>>8) into shared memory (unstable order —
// max is order-exact, sum order shifts ~1ulp). All warps then gather keys in
// the same tile 0->7 order, so the concurrently-resident blocks of a (b,h)
// keep a ~1-2 tile (64-128KB) hot set that fits L1 instead of streaming the
// full 512KB K slice from L2. Inner gather math identical to R5.
// ---------------------------------------------------------------------------
__global__ void k_sample_topk(const float* __restrict__ Q, const float* __restrict__ K,
                              const float* __restrict__ V, const int* __restrict__ idx,
                              float* __restrict__ out) {
    __shared__ float sv[8][64];
    __shared__ unsigned short sjb[8][SS];   // per-warp tile-sorted sample indices
    __shared__ int scn[8][8];               // per-warp per-tile counters
    __shared__ int   isLast;
    // top-k shared state (only used by the last block per bh)
    __shared__ unsigned su[LL];
    __shared__ int hist[256];
    __shared__ int scnt[2];
    __shared__ unsigned long long keys[128];
    __shared__ int eqbuf[256];
    __shared__ int cgt, ceq;
    __shared__ int stop[UU];
    __shared__ int win[UU];
    __shared__ float mean[64];

    int t = threadIdx.x, lane = t & 31, warp = t >> 5;
    int gw = blockIdx.x * 8 + warp;
    int l  = gw & (LL-1);
    int bh = gw >> 11;
    int b = bh >> 3, h = bh & 7;
    int grp = lane >> 3, lg = lane & 7;

    const float* qrow = Q + (((size_t)b*LL + l)*HH + h)*DD;
    float4 q0 = *(const float4*)(qrow + lg*8);
    float4 q1 = *(const float4*)(qrow + lg*8 + 4);

    // V row for this l (coalesced float2 per lane)
    float2 vv = *(const float2*)(V + (((size_t)b*LL + l)*HH + h)*DD + lane*2);
    sv[warp][lane*2] = vv.x; sv[warp][lane*2+1] = vv.y;

    // ---- warp-local counting sort of the 80 sample indices by key tile ----
    const int* irow = idx + l*SS;
    int j0 = irow[lane];
    int j1 = irow[lane + 32];
    int j2 = (lane < 16) ? irow[lane + 64] : 0;
    if (lane < 8) scn[warp][lane] = 0;
    __syncwarp();
    atomicAdd(&scn[warp][j0 >> 8], 1);
    atomicAdd(&scn[warp][j1 >> 8], 1);
    if (lane < 16) atomicAdd(&scn[warp][j2 >> 8], 1);
    __syncwarp();
    if (lane < 8) {
        int c = scn[warp][lane];
        int pre = c;
        #pragma unroll
        for (int o = 1; o < 8; o <<= 1) {
            int v = __shfl_up_sync(0x000000ffu, pre, o);
            if (lane >= o) pre += v;
        }
        scn[warp][lane] = pre - c;       // exclusive start per tile
    }
    __syncwarp();
    { int p = atomicAdd(&scn[warp][j0 >> 8], 1); sjb[warp][p] = (unsigned short)j0; }
    { int p = atomicAdd(&scn[warp][j1 >> 8], 1); sjb[warp][p] = (unsigned short)j1; }
    if (lane < 16) { int p = atomicAdd(&scn[warp][j2 >> 8], 1); sjb[warp][p] = (unsigned short)j2; }
    __syncwarp();

    // ---- gather loop (identical shape to R5; indices now tile-sorted) ----
    float vmax = -CUDART_INF_F, vsum = 0.f;
    #pragma unroll 5
    for (int it = 0; it < SS/4; ++it) {
        int j = sjb[warp][it*4 + grp];
        const float* krow = K + (((size_t)b*LL + j)*HH + h)*DD + lg*8;
        float4 k0 = *(const float4*)(krow);
        float4 k1 = *(const float4*)(krow + 4);
        float p = q0.x*k0.x + q0.y*k0.y + q0.z*k0.z + q0.w*k0.w
                + q1.x*k1.x + q1.y*k1.y + q1.z*k1.z + q1.w*k1.w;
        p += __shfl_xor_sync(0xffffffffu, p, 4);
        p += __shfl_xor_sync(0xffffffffu, p, 2);
        p += __shfl_xor_sync(0xffffffffu, p, 1);
        vmax = fmaxf(vmax, p);
        vsum += p;
    }
    vmax = fmaxf(vmax, __shfl_xor_sync(0xffffffffu, vmax, 8));
    vmax = fmaxf(vmax, __shfl_xor_sync(0xffffffffu, vmax, 16));
    vsum += __shfl_xor_sync(0xffffffffu, vsum, 8);
    vsum += __shfl_xor_sync(0xffffffffu, vsum, 16);
    if (lane == 0) g_M[gw] = vmax - vsum * (1.0f/(float)LL);

    __syncthreads();
    if (t < 64) {
        float s = sv[0][t] + sv[1][t] + sv[2][t] + sv[3][t]
                + sv[4][t] + sv[5][t] + sv[6][t] + sv[7][t];
        atomicAdd(&g_vmean[bh*64 + t], s);
    }

    // ---- completion protocol: last block of this bh runs top-k inline ----
    __threadfence();
    __syncthreads();
    if (t == 0) {
        int old = atomicAdd(&g_cb[bh], 1);
        isLast = (old == BLKS_PER_BH - 1);
    }
    __syncthreads();
    if (!isLast) return;
    if (t == 0) g_cb[bh] = 0;    // self-reset for next graph replay

    // ======================= top-k body (last block) =======================
    if (t < 64) {
        mean[t] = g_vmean[bh*64 + t] * (1.0f/(float)LL);
        g_vmean[bh*64 + t] = 0.f;
    }
    for (int i = t; i < LL; i += 256) {
        unsigned bb = __float_as_uint(g_M[bh*LL + i]);
        su[i] = (bb & 0x80000000u) ? ~bb : (bb | 0x80000000u);
    }
    __syncthreads();

    // broadcast-fill all 80 output rows with V_mean (winners overwritten later)
    for (int e = t; e < UU*64; e += 256) {
        int j = e >> 6, d = e & 63;
        out[(((size_t)b*UU + j)*HH + h)*DD + d] = mean[d];
    }

    // 4-pass byte radix: T = 80th-largest transformed value
    unsigned prefix = 0, prefmask = 0;
    int need = UU;
    for (int pass = 0; pass < 4; ++pass) {
        int shift = 24 - pass*8;
        hist[t] = 0;
        __syncthreads();
        for (int i = t; i < LL; i += 256) {
            unsigned u = su[i];
            if ((u & prefmask) == prefix) atomicAdd(&hist[(u >> shift) & 0xFF], 1);
        }
        __syncthreads();
        if (t < 32) {
            int base = 255 - t*8;
            int s = 0;
            #pragma unroll
            for (int e = 0; e < 8; ++e) s += hist[base - e];
            int pre = s;
            #pragma unroll
            for (int o = 1; o < 32; o <<= 1) {
                int v = __shfl_up_sync(0xffffffffu, pre, o);
                if (lane >= o) pre += v;
            }
            int excl = pre - s;
            if (excl < need && need <= pre) {
                int acc = excl;
                #pragma unroll
                for (int e = 0; e < 8; ++e) {
                    int hb = hist[base - e];
                    if (acc + hb >= need) { scnt[0] = base - e; scnt[1] = acc; break; }
                    acc += hb;
                }
            }
        }
        __syncthreads();
        prefix |= ((unsigned)scnt[0]) << shift;
        prefmask |= 0xFFu << shift;
        need -= scnt[1];
        __syncthreads();
    }
    unsigned T = prefix;

    if (t == 0) { cgt = 0; ceq = 0; }
    __syncthreads();
    for (int i = t; i < LL; i += 256) {
        unsigned u = su[i];
        if (u > T) {
            int p = atomicAdd(&cgt, 1);
            keys[p] = ((unsigned long long)u << 32) | (unsigned)(~i);
        } else if (u == T) {
            int p = atomicAdd(&ceq, 1);
            if (p < 256) eqbuf[p] = i;
        }
    }
    __syncthreads();
    if (t == 0) {
        int base = cgt;
        int ce = min(ceq, 256);
        for (int k = 0; k < need; ++k) {
            int mi = 0x7fffffff, mp = -1;
            for (int e = 0; e < ce; ++e)
                if (eqbuf[e] < mi) { mi = eqbuf[e]; mp = e; }
            keys[base + k] = ((unsigned long long)T << 32) | (unsigned)(~mi);
            eqbuf[mp] = 0x7fffffff;
        }
    }
    for (int i = t; i < 128; i += 256) if (i >= UU) keys[i] = 0ULL;
    __syncthreads();

    // bitonic sort, 128 elements, descending (=> value desc, index asc)
    for (int ksz = 2; ksz <= 128; ksz <<= 1) {
        for (int jst = ksz >> 1; jst > 0; jst >>= 1) {
            __syncthreads();
            if (t < 128) {
                int ixj = t ^ jst;
                if (ixj > t) {
                    unsigned long long a = keys[t], c = keys[ixj];
                    bool up = (t & ksz) == 0;
                    if (up ? (a < c) : (a > c)) { keys[t] = c; keys[ixj] = a; }
                }
            }
        }
    }
    __syncthreads();

    if (t < UU) {
        stop[t] = (int)(~(unsigned)(keys[t] & 0xffffffffu));
        win[t] = -1;
    }
    __syncthreads();
    if (t == 0) {
        for (int u = 0; u < UU; ++u) { int jj = min(stop[u], UU-1); win[jj] = u; }
        int n = 0;
        for (int jj = 0; jj < UU; ++jj) {
            if (win[jj] >= 0) {
                g_wl[bh*UU + n] = stop[win[jj]];
                g_wj[bh*UU + n] = jj;
                n++;
            }
        }
        g_nw[bh] = n;
    }
}

// ---------------------------------------------------------------------------
// Kernel 2: split-K attention partials for winner rows with last-split-block
// combine. SPLIT=16, CHUNK=128, 256 threads, grid (bh, UST, SPLIT).
// (Measured 19.3us in R6/R7 — carried over verbatim.)
// ---------------------------------------------------------------------------
__global__ void k_attn(const float* __restrict__ Q, const float* __restrict__ K,
                       const float* __restrict__ V, float* __restrict__ out) {
    int bh = blockIdx.x;
    int n = g_nw[bh];
    int b = bh >> 3, h = bh & 7;
    int sp = blockIdx.z, k0 = sp * CHUNK;

    __shared__ float q[DD];
    __shared__ float p[CHUNK];
    __shared__ float red[8];
    __shared__ float ac[4][64];
    __shared__ int lastf;
    int t = threadIdx.x, lane = t & 31, warp = t >> 5;
    int grp = lane >> 3, lg = lane & 7;

    for (int u = blockIdx.y; u < n; u += UST) {
        int l = g_wl[bh*UU + u];
        if (t < DD) q[t] = Q[(((size_t)b*LL + l)*HH + h)*DD + t];
        __syncthreads();
        float4 q0 = ((float4*)q)[lg*2];
        float4 q1 = ((float4*)q)[lg*2 + 1];

        // scores: each warp owns 16 keys, 4 per iteration (one per 8-lane group)
        float lmax = -CUDART_INF_F;
        #pragma unroll
        for (int it = 0; it < 4; ++it) {
            int kk = warp*16 + it*4 + grp;
            const float* kr = K + (((size_t)b*LL + k0 + kk)*HH + h)*DD + lg*8;
            float4 k0v = *(const float4*)kr;
            float4 k1v = *(const float4*)(kr + 4);
            float s = q0.x*k0v.x + q0.y*k0v.y + q0.z*k0v.z + q0.w*k0v.w
                    + q1.x*k1v.x + q1.y*k1v.y + q1.z*k1v.z + q1.w*k1v.w;
            s += __shfl_xor_sync(0xffffffffu, s, 4);
            s += __shfl_xor_sync(0xffffffffu, s, 2);
            s += __shfl_xor_sync(0xffffffffu, s, 1);
            s *= 0.125f;                 // 1/sqrt(64)
            if (lg == 0) p[kk] = s;
            lmax = fmaxf(lmax, s);
        }
        lmax = fmaxf(lmax, __shfl_xor_sync(0xffffffffu, lmax, 8));
        lmax = fmaxf(lmax, __shfl_xor_sync(0xffffffffu, lmax, 16));
        if (lane == 0) red[warp] = lmax;
        __syncthreads();
        if (t == 0) { float m = red[0]; for (int w = 1; w < 8; ++w) m = fmaxf(m, red[w]); red[0] = m; }
        __syncthreads();
        float m = red[0];
        __syncthreads();

        float e = 0.f;
        if (t < CHUNK) { e = __expf(p[t] - m); p[t] = e; }
        float ls = e;
        #pragma unroll
        for (int o = 16; o; o >>= 1) ls += __shfl_xor_sync(0xffffffffu, ls, o);
        if (lane == 0) red[warp] = ls;
        __syncthreads();
        float ssumv = red[0]+red[1]+red[2]+red[3]+red[4]+red[5]+red[6]+red[7];

        // partial PV: 4 key-groups x 64 d-threads, coalesced V reads
        int g4 = t >> 6, d = t & 63;
        float acc = 0.f;
        #pragma unroll 8
        for (int kk = g4; kk < CHUNK; kk += 4)
            acc += p[kk] * V[(((size_t)b*LL + k0 + kk)*HH + h)*DD + d];
        ac[g4][d] = acc;
        __syncthreads();
        int base = (bh*UU + u)*SPLIT + sp;
        if (t < 64)
            g_pv[(size_t)base*DD + t] = ac[0][t] + ac[1][t] + ac[2][t] + ac[3][t];
        if (t == 0) { g_pmax[base] = m; g_psum[base] = ssumv; }

        // ---- last split block for this (bh,u) combines and writes out ----
        __threadfence();
        __syncthreads();
        if (t == 0) {
            int old = atomicAdd(&g_cu[bh*UU + u], 1);
            lastf = (old == SPLIT - 1);
        }
        __syncthreads();
        if (lastf) {
            if (t == 0) g_cu[bh*UU + u] = 0;   // self-reset for replay
            if (t < 64) {
                int cb = (bh*UU + u)*SPLIT;
                float mm = -CUDART_INF_F;
                #pragma unroll
                for (int i = 0; i < SPLIT; ++i) mm = fmaxf(mm, g_pmax[cb + i]);
                float s = 0.f, pv = 0.f;
                #pragma unroll
                for (int i = 0; i < SPLIT; ++i) {
                    float w = __expf(g_pmax[cb + i] - mm);
                    s  += g_psum[cb + i] * w;
                    pv += g_pv[(size_t)(cb + i)*DD + t] * w;
                }
                int j = g_wj[bh*UU + u];
                out[(((size_t)b*UU + j)*HH + h)*DD + t] = pv / s;
            }
        }
        __syncthreads();                 // smem reuse across u iterations
    }
}

// ---------------------------------------------------------------------------
extern "C" void kernel_launch(void* const* d_in, const int* in_sizes, int n_in,
                              void* d_out, int out_size) {
    const float* Q   = (const float*)d_in[0];
    const float* K   = (const float*)d_in[1];
    const float* V   = (const float*)d_in[2];
    const int*   idx = (const int*)d_in[3];
    float* out = (float*)d_out;

    // maximize L1D for the gather kernel (smem footprint is small)
    cudaFuncSetAttribute(k_sample_topk,
                         cudaFuncAttributePreferredSharedMemoryCarveout,
                         cudaSharedmemCarveoutMaxL1);

    k_sample_topk<<<(BB*HH*LL)/8, 256>>>(Q, K, V, idx, out);
    dim3 ga(BHN, UST, SPLIT);
    k_attn<<<ga, 256>>>(Q, K, V, out);
}

// round 9
// speedup vs baseline: 2.2037x; 2.1278x over previous
#include <cuda_runtime.h>
#include <cuda_bf16.h>
#include <math_constants.h>

// Problem constants (fixed by the benchmark)
#define BB 2
#define LL 2048
#define HH 8
#define DD 64
#define UU 80
#define SS 80
#define BHN (BB*HH)
#define SPLIT 16
#define CHUNK (LL/SPLIT)      // 128 keys per split block
#define UST 8                 // u-stride for winner loop
#define BLKS_PER_BH 256       // k_sample blocks per (b,h)

// Scratch (device globals; zero-initialized at module load)
__device__ float g_M[BB*HH*LL];           // sparsity measure M[b,h,l]
__device__ float g_vmean[BHN*DD];         // V column sums (atomic), re-zeroed after use
__device__ int   g_cb[BHN];               // per-bh completion counter (self-reset)
__device__ int   g_cu[BHN*UU];            // per-(bh,u) split counter (self-reset)
__device__ int   g_nw[BHN];               // winners per (b,h)
__device__ int   g_wl[BHN*UU];            // winner: source token l
__device__ int   g_wj[BHN*UU];            // winner: output slot j
__device__ float g_pmax[BHN*UU*SPLIT];    // split-softmax partial max
__device__ float g_psum[BHN*UU*SPLIT];    // split-softmax partial sum(exp)
__device__ float g_pv  [BHN*UU*SPLIT*DD]; // split partial (unnormalized) PV

// ---------------------------------------------------------------------------
// Kernel 1: sampled scores -> M[b,h,l] fused with V column sums; last block
// per (b,h) runs top-80 (radix select + bitonic, exact jax.lax.top_k
// semantics), winner replay, V_mean fill.
//
// Warp-local counting sort orders each row's 80 samples by key tile (j>>8);
// all warps then gather in the same tile 0->7 order so concurrently-resident
// same-bh blocks share a small hot key set (L1). Gather math identical to the
// validated R5 kernel. NO L1-carveout hint: the R8 experiment showed it
// collapses occupancy to 1 CTA/SM (smem ~15.5KB static) and triples runtime.
// ---------------------------------------------------------------------------
__global__ void k_sample_topk(const float* __restrict__ Q, const float* __restrict__ K,
                              const float* __restrict__ V, const int* __restrict__ idx,
                              float* __restrict__ out) {
    __shared__ float sv[8][64];
    __shared__ unsigned short sjb[8][SS];   // per-warp tile-sorted sample indices
    __shared__ int scn[8][8];               // per-warp per-tile counters
    __shared__ int   isLast;
    // top-k shared state (only used by the last block per bh)
    __shared__ unsigned su[LL];
    __shared__ int hist[256];
    __shared__ int scnt[2];
    __shared__ unsigned long long keys[128];
    __shared__ int eqbuf[256];
    __shared__ int cgt, ceq;
    __shared__ int stop[UU];
    __shared__ int win[UU];
    __shared__ float mean[64];

    int t = threadIdx.x, lane = t & 31, warp = t >> 5;
    int gw = blockIdx.x * 8 + warp;
    int l  = gw & (LL-1);
    int bh = gw >> 11;
    int b = bh >> 3, h = bh & 7;
    int grp = lane >> 3, lg = lane & 7;

    const float* qrow = Q + (((size_t)b*LL + l)*HH + h)*DD;
    float4 q0 = *(const float4*)(qrow + lg*8);
    float4 q1 = *(const float4*)(qrow + lg*8 + 4);

    // V row for this l (coalesced float2 per lane)
    float2 vv = *(const float2*)(V + (((size_t)b*LL + l)*HH + h)*DD + lane*2);
    sv[warp][lane*2] = vv.x; sv[warp][lane*2+1] = vv.y;

    // ---- warp-local counting sort of the 80 sample indices by key tile ----
    const int* irow = idx + l*SS;
    int j0 = irow[lane];
    int j1 = irow[lane + 32];
    int j2 = (lane < 16) ? irow[lane + 64] : 0;
    if (lane < 8) scn[warp][lane] = 0;
    __syncwarp();
    atomicAdd(&scn[warp][j0 >> 8], 1);
    atomicAdd(&scn[warp][j1 >> 8], 1);
    if (lane < 16) atomicAdd(&scn[warp][j2 >> 8], 1);
    __syncwarp();
    if (lane < 8) {
        int c = scn[warp][lane];
        int pre = c;
        #pragma unroll
        for (int o = 1; o < 8; o <<= 1) {
            int v = __shfl_up_sync(0x000000ffu, pre, o);
            if (lane >= o) pre += v;
        }
        scn[warp][lane] = pre - c;       // exclusive start per tile
    }
    __syncwarp();
    { int p = atomicAdd(&scn[warp][j0 >> 8], 1); sjb[warp][p] = (unsigned short)j0; }
    { int p = atomicAdd(&scn[warp][j1 >> 8], 1); sjb[warp][p] = (unsigned short)j1; }
    if (lane < 16) { int p = atomicAdd(&scn[warp][j2 >> 8], 1); sjb[warp][p] = (unsigned short)j2; }
    __syncwarp();

    // ---- gather loop (identical shape to R5; indices now tile-sorted) ----
    float vmax = -CUDART_INF_F, vsum = 0.f;
    #pragma unroll 5
    for (int it = 0; it < SS/4; ++it) {
        int j = sjb[warp][it*4 + grp];
        const float* krow = K + (((size_t)b*LL + j)*HH + h)*DD + lg*8;
        float4 k0 = *(const float4*)(krow);
        float4 k1 = *(const float4*)(krow + 4);
        float p = q0.x*k0.x + q0.y*k0.y + q0.z*k0.z + q0.w*k0.w
                + q1.x*k1.x + q1.y*k1.y + q1.z*k1.z + q1.w*k1.w;
        p += __shfl_xor_sync(0xffffffffu, p, 4);
        p += __shfl_xor_sync(0xffffffffu, p, 2);
        p += __shfl_xor_sync(0xffffffffu, p, 1);
        vmax = fmaxf(vmax, p);
        vsum += p;
    }
    vmax = fmaxf(vmax, __shfl_xor_sync(0xffffffffu, vmax, 8));
    vmax = fmaxf(vmax, __shfl_xor_sync(0xffffffffu, vmax, 16));
    vsum += __shfl_xor_sync(0xffffffffu, vsum, 8);
    vsum += __shfl_xor_sync(0xffffffffu, vsum, 16);
    if (lane == 0) g_M[gw] = vmax - vsum * (1.0f/(float)LL);

    __syncthreads();
    if (t < 64) {
        float s = sv[0][t] + sv[1][t] + sv[2][t] + sv[3][t]
                + sv[4][t] + sv[5][t] + sv[6][t] + sv[7][t];
        atomicAdd(&g_vmean[bh*64 + t], s);
    }

    // ---- completion protocol: last block of this bh runs top-k inline ----
    __threadfence();
    __syncthreads();
    if (t == 0) {
        int old = atomicAdd(&g_cb[bh], 1);
        isLast = (old == BLKS_PER_BH - 1);
    }
    __syncthreads();
    if (!isLast) return;
    if (t == 0) g_cb[bh] = 0;    // self-reset for next graph replay

    // ======================= top-k body (last block) =======================
    if (t < 64) {
        mean[t] = g_vmean[bh*64 + t] * (1.0f/(float)LL);
        g_vmean[bh*64 + t] = 0.f;
    }
    for (int i = t; i < LL; i += 256) {
        unsigned bb = __float_as_uint(g_M[bh*LL + i]);
        su[i] = (bb & 0x80000000u) ? ~bb : (bb | 0x80000000u);
    }
    __syncthreads();

    // broadcast-fill all 80 output rows with V_mean (winners overwritten later)
    for (int e = t; e < UU*64; e += 256) {
        int j = e >> 6, d = e & 63;
        out[(((size_t)b*UU + j)*HH + h)*DD + d] = mean[d];
    }

    // 4-pass byte radix: T = 80th-largest transformed value
    unsigned prefix = 0, prefmask = 0;
    int need = UU;
    for (int pass = 0; pass < 4; ++pass) {
        int shift = 24 - pass*8;
        hist[t] = 0;
        __syncthreads();
        for (int i = t; i < LL; i += 256) {
            unsigned u = su[i];
            if ((u & prefmask) == prefix) atomicAdd(&hist[(u >> shift) & 0xFF], 1);
        }
        __syncthreads();
        if (t < 32) {
            int base = 255 - t*8;
            int s = 0;
            #pragma unroll
            for (int e = 0; e < 8; ++e) s += hist[base - e];
            int pre = s;
            #pragma unroll
            for (int o = 1; o < 32; o <<= 1) {
                int v = __shfl_up_sync(0xffffffffu, pre, o);
                if (lane >= o) pre += v;
            }
            int excl = pre - s;
            if (excl < need && need <= pre) {
                int acc = excl;
                #pragma unroll
                for (int e = 0; e < 8; ++e) {
                    int hb = hist[base - e];
                    if (acc + hb >= need) { scnt[0] = base - e; scnt[1] = acc; break; }
                    acc += hb;
                }
            }
        }
        __syncthreads();
        prefix |= ((unsigned)scnt[0]) << shift;
        prefmask |= 0xFFu << shift;
        need -= scnt[1];
        __syncthreads();
    }
    unsigned T = prefix;

    if (t == 0) { cgt = 0; ceq = 0; }
    __syncthreads();
    for (int i = t; i < LL; i += 256) {
        unsigned u = su[i];
        if (u > T) {
            int p = atomicAdd(&cgt, 1);
            keys[p] = ((unsigned long long)u << 32) | (unsigned)(~i);
        } else if (u == T) {
            int p = atomicAdd(&ceq, 1);
            if (p < 256) eqbuf[p] = i;
        }
    }
    __syncthreads();
    if (t == 0) {
        int base = cgt;
        int ce = min(ceq, 256);
        for (int k = 0; k < need; ++k) {
            int mi = 0x7fffffff, mp = -1;
            for (int e = 0; e < ce; ++e)
                if (eqbuf[e] < mi) { mi = eqbuf[e]; mp = e; }
            keys[base + k] = ((unsigned long long)T << 32) | (unsigned)(~mi);
            eqbuf[mp] = 0x7fffffff;
        }
    }
    for (int i = t; i < 128; i += 256) if (i >= UU) keys[i] = 0ULL;
    __syncthreads();

    // bitonic sort, 128 elements, descending (=> value desc, index asc)
    for (int ksz = 2; ksz <= 128; ksz <<= 1) {
        for (int jst = ksz >> 1; jst > 0; jst >>= 1) {
            __syncthreads();
            if (t < 128) {
                int ixj = t ^ jst;
                if (ixj > t) {
                    unsigned long long a = keys[t], c = keys[ixj];
                    bool up = (t & ksz) == 0;
                    if (up ? (a < c) : (a > c)) { keys[t] = c; keys[ixj] = a; }
                }
            }
        }
    }
    __syncthreads();

    if (t < UU) {
        stop[t] = (int)(~(unsigned)(keys[t] & 0xffffffffu));
        win[t] = -1;
    }
    __syncthreads();
    if (t == 0) {
        for (int u = 0; u < UU; ++u) { int jj = min(stop[u], UU-1); win[jj] = u; }
        int n = 0;
        for (int jj = 0; jj < UU; ++jj) {
            if (win[jj] >= 0) {
                g_wl[bh*UU + n] = stop[win[jj]];
                g_wj[bh*UU + n] = jj;
                n++;
            }
        }
        g_nw[bh] = n;
    }
}

// ---------------------------------------------------------------------------
// Kernel 2: split-K attention partials for winner rows with last-split-block
// combine. SPLIT=16, CHUNK=128, 256 threads, grid (bh, UST, SPLIT).
// (Measured 19.1-19.5us across R6-R8 — carried over verbatim.)
// ---------------------------------------------------------------------------
__global__ void k_attn(const float* __restrict__ Q, const float* __restrict__ K,
                       const float* __restrict__ V, float* __restrict__ out) {
    int bh = blockIdx.x;
    int n = g_nw[bh];
    int b = bh >> 3, h = bh & 7;
    int sp = blockIdx.z, k0 = sp * CHUNK;

    __shared__ float q[DD];
    __shared__ float p[CHUNK];
    __shared__ float red[8];
    __shared__ float ac[4][64];
    __shared__ int lastf;
    int t = threadIdx.x, lane = t & 31, warp = t >> 5;
    int grp = lane >> 3, lg = lane & 7;

    for (int u = blockIdx.y; u < n; u += UST) {
        int l = g_wl[bh*UU + u];
        if (t < DD) q[t] = Q[(((size_t)b*LL + l)*HH + h)*DD + t];
        __syncthreads();
        float4 q0 = ((float4*)q)[lg*2];
        float4 q1 = ((float4*)q)[lg*2 + 1];

        // scores: each warp owns 16 keys, 4 per iteration (one per 8-lane group)
        float lmax = -CUDART_INF_F;
        #pragma unroll
        for (int it = 0; it < 4; ++it) {
            int kk = warp*16 + it*4 + grp;
            const float* kr = K + (((size_t)b*LL + k0 + kk)*HH + h)*DD + lg*8;
            float4 k0v = *(const float4*)kr;
            float4 k1v = *(const float4*)(kr + 4);
            float s = q0.x*k0v.x + q0.y*k0v.y + q0.z*k0v.z + q0.w*k0v.w
                    + q1.x*k1v.x + q1.y*k1v.y + q1.z*k1v.z + q1.w*k1v.w;
            s += __shfl_xor_sync(0xffffffffu, s, 4);
            s += __shfl_xor_sync(0xffffffffu, s, 2);
            s += __shfl_xor_sync(0xffffffffu, s, 1);
            s *= 0.125f;                 // 1/sqrt(64)
            if (lg == 0) p[kk] = s;
            lmax = fmaxf(lmax, s);
        }
        lmax = fmaxf(lmax, __shfl_xor_sync(0xffffffffu, lmax, 8));
        lmax = fmaxf(lmax, __shfl_xor_sync(0xffffffffu, lmax, 16));
        if (lane == 0) red[warp] = lmax;
        __syncthreads();
        if (t == 0) { float m = red[0]; for (int w = 1; w < 8; ++w) m = fmaxf(m, red[w]); red[0] = m; }
        __syncthreads();
        float m = red[0];
        __syncthreads();

        float e = 0.f;
        if (t < CHUNK) { e = __expf(p[t] - m); p[t] = e; }
        float ls = e;
        #pragma unroll
        for (int o = 16; o; o >>= 1) ls += __shfl_xor_sync(0xffffffffu, ls, o);
        if (lane == 0) red[warp] = ls;
        __syncthreads();
        float ssumv = red[0]+red[1]+red[2]+red[3]+red[4]+red[5]+red[6]+red[7];

        // partial PV: 4 key-groups x 64 d-threads, coalesced V reads
        int g4 = t >> 6, d = t & 63;
        float acc = 0.f;
        #pragma unroll 8
        for (int kk = g4; kk < CHUNK; kk += 4)
            acc += p[kk] * V[(((size_t)b*LL + k0 + kk)*HH + h)*DD + d];
        ac[g4][d] = acc;
        __syncthreads();
        int base = (bh*UU + u)*SPLIT + sp;
        if (t < 64)
            g_pv[(size_t)base*DD + t] = ac[0][t] + ac[1][t] + ac[2][t] + ac[3][t];
        if (t == 0) { g_pmax[base] = m; g_psum[base] = ssumv; }

        // ---- last split block for this (bh,u) combines and writes out ----
        __threadfence();
        __syncthreads();
        if (t == 0) {
            int old = atomicAdd(&g_cu[bh*UU + u], 1);
            lastf = (old == SPLIT - 1);
        }
        __syncthreads();
        if (lastf) {
            if (t == 0) g_cu[bh*UU + u] = 0;   // self-reset for replay
            if (t < 64) {
                int cb = (bh*UU + u)*SPLIT;
                float mm = -CUDART_INF_F;
                #pragma unroll
                for (int i = 0; i < SPLIT; ++i) mm = fmaxf(mm, g_pmax[cb + i]);
                float s = 0.f, pv = 0.f;
                #pragma unroll
                for (int i = 0; i < SPLIT; ++i) {
                    float w = __expf(g_pmax[cb + i] - mm);
                    s  += g_psum[cb + i] * w;
                    pv += g_pv[(size_t)(cb + i)*DD + t] * w;
                }
                int j = g_wj[bh*UU + u];
                out[(((size_t)b*UU + j)*HH + h)*DD + t] = pv / s;
            }
        }
        __syncthreads();                 // smem reuse across u iterations
    }
}

// ---------------------------------------------------------------------------
extern "C" void kernel_launch(void* const* d_in, const int* in_sizes, int n_in,
                              void* d_out, int out_size) {
    const float* Q   = (const float*)d_in[0];
    const float* K   = (const float*)d_in[1];
    const float* V   = (const float*)d_in[2];
    const int*   idx = (const int*)d_in[3];
    float* out = (float*)d_out;

    k_sample_topk<<<(BB*HH*LL)/8, 256>>>(Q, K, V, idx, out);
    dim3 ga(BHN, UST, SPLIT);
    k_attn<<<ga, 256>>>(Q, K, V, out);
}